// round 13
// baseline (speedup 1.0000x reference)
#include <cuda_runtime.h>
#include <cstdint>
#include <stdint.h>
#include <math.h>

#define Bb   8
#define Ss   1024
#define Dd   768
#define Hh   12
#define HDh  64
#define DFF  3072
#define LL   6
#define MOFF (Bb*Ss*Dd)      // 6291456, size of one of Q/K/V

// ---------------- scratch (all activation/weight tensors in "P-layout":
// within each 32-aligned feature block, logical k stored at (k&3)*8 + (k>>2)) --------
__device__ float gX   [Bb*Ss*Dd];
__device__ float gXr  [Bb*Ss*Dd];
__device__ float gQKV [3*Bb*Ss*Dd];
__device__ float gHb  [Bb*Ss*Dd];
__device__ float gY1  [Bb*Ss*Dd];
__device__ float gY1r [Bb*Ss*Dd];
__device__ float gF   [Bb*Ss*DFF];
__device__ float gWqkv[LL*3*Dd*Dd];
__device__ float gBqkv[LL*3*Dd];
__device__ float gW1r [LL*DFF*Dd];
__device__ float gW2r [LL*Dd*DFF];
__device__ float gB1p [LL*DFF];
__device__ float gB2p [LL*Dd];
__device__ float gLn1g[LL*Dd];
__device__ float gLn1b[LL*Dd];
__device__ float gLn2g[LL*Dd];
__device__ float gLn2b[LL*Dd];

// ---------------- helpers ----------------
__device__ __forceinline__ int inv32(int j) { return ((j & 7) << 2) | (j >> 3); }

__device__ __forceinline__ float f2tf32f(float f) {
    unsigned u;
    asm("cvt.rna.tf32.f32 %0, %1;" : "=r"(u) : "f"(f));
    return __uint_as_float(u);
}
__device__ __forceinline__ unsigned f2tf32u(float f) {
    unsigned u;
    asm("cvt.rna.tf32.f32 %0, %1;" : "=r"(u) : "f"(f));
    return u;
}

__device__ __forceinline__ void mma_tf32(float c[4], unsigned a0, unsigned a1, unsigned a2, unsigned a3,
                                         unsigned b0, unsigned b1) {
    asm volatile(
        "mma.sync.aligned.m16n8k8.row.col.f32.tf32.tf32.f32 "
        "{%0,%1,%2,%3}, {%4,%5,%6,%7}, {%8,%9}, {%0,%1,%2,%3};\n"
        : "+f"(c[0]), "+f"(c[1]), "+f"(c[2]), "+f"(c[3])
        : "r"(a0), "r"(a1), "r"(a2), "r"(a3), "r"(b0), "r"(b1));
}

__device__ __forceinline__ void cp16(unsigned* smem_dst, const void* gmem_src) {
    unsigned s = (unsigned)__cvta_generic_to_shared(smem_dst);
    asm volatile("cp.async.cg.shared.global [%0], [%1], 16;\n" :: "r"(s), "l"(gmem_src));
}
#define CP_COMMIT asm volatile("cp.async.commit_group;\n" ::)
#define CP_WAIT0  asm volatile("cp.async.wait_group 0;\n" ::)

// ---------------- prep: permute+round weights, permute params ----------------
__global__ void perm_weight(float* __restrict__ dst, const float* __restrict__ src,
                            int cols, long dstL, long srcL) {
    const int l  = blockIdx.y;
    const int rp = blockIdx.x;
    const int r  = (rp & ~31) | inv32(rp & 31);
    const float* s = src + l * srcL + (long)r * cols;
    float* d       = dst + l * dstL + (long)rp * cols;
    for (int cp = threadIdx.x; cp < cols; cp += 256) {
        int c = (cp & ~31) | inv32(cp & 31);
        d[cp] = f2tf32f(s[c]);
    }
}

__global__ void perm_vec(float* __restrict__ dst, const float* __restrict__ src) {
    int i = blockIdx.x * blockDim.x + threadIdx.x;
    dst[i] = src[(i & ~31) | inv32(i & 31)];
}

__global__ void pack_qkv_b(float* __restrict__ dst, const float* __restrict__ bq,
                           const float* __restrict__ bk, const float* __restrict__ bv) {
    int i = blockIdx.x * blockDim.x + threadIdx.x;     // phys over LL*2304
    int pos = (i & ~31) | inv32(i & 31);
    int l = pos / 2304, n = pos % 2304;
    dst[i] = (n < 768) ? bq[l * 768 + n] : (n < 1536) ? bk[l * 768 + n - 768] : bv[l * 768 + n - 1536];
}

// ---------------- embedding (writes P-layout) ----------------
__global__ void embed_kernel(const int* __restrict__ ids, const float* __restrict__ emb,
                             const float* __restrict__ pe, float* __restrict__ x,
                             float* __restrict__ xr) {
    int i  = blockIdx.x * blockDim.x + threadIdx.x;
    int dp = i % Dd;
    int bs = i / Dd;
    int s  = bs % Ss;
    int d  = (dp & ~31) | inv32(dp & 31);
    float v = emb[(size_t)ids[bs] * Dd + d] + pe[(size_t)s * Dd + d];
    x[i]  = v;
    xr[i] = f2tf32f(v);
}

// ============ TF32 NT GEMM, cp.async double-buffered, BM=256 x BN=128, 512 threads ============
// All operands in P-layout, pre-rounded. BK=32. 16 warps (4x4 of 64x32 warp tiles), 1 CTA/SM
// (same 16 warps/SM as before, but B-operand L2 traffic halves: grid_y = M/256).
// Loop: WAIT0 -> sync -> ISSUE(i+1) -> COMPUTE(i).
// Stage = (256 + 128) * 36 = 13824 words = 55296 B; 2 stages = 110592 B.
template<bool BIAS, bool RELU, bool ROUND, bool SPLIT>
__global__ __launch_bounds__(512, 1) void gemm_tf32_nt(
    int M, int N, int K,
    const float* __restrict__ A, int lda,
    const float* __restrict__ B, int ldb,
    float* __restrict__ C, int ldc,
    const float* __restrict__ bias)
{
    extern __shared__ unsigned sm[];
    const unsigned* Ap = (const unsigned*)(A + (size_t)(blockIdx.y * 256) * lda);
    const unsigned* Bp = (const unsigned*)(B + (size_t)(blockIdx.x * 128) * ldb);
    const int tid = threadIdx.x;
    const int lane = tid & 31, warp = tid >> 5;          // warp 0..15
    const int wm = (warp >> 2) * 64, wn = (warp & 3) * 32;
    const int grp = lane >> 2, tig = lane & 3;
    const int lrow = tid >> 3;            // 0..63
    const int lc4  = (tid & 7) * 4;       // 0..28

    float acc[4][4][4] = {};
    const int nk = K >> 5;

    auto ISSUE = [&](int i) {
        int k0 = i << 5;
        unsigned* base = sm + (i & 1) * 13824;
        #pragma unroll
        for (int p = 0; p < 4; p++) {                    // A: 256 rows
            int r = lrow + p * 64;
            cp16(base + r * 36 + lc4, Ap + (size_t)r * lda + k0 + lc4);
        }
        #pragma unroll
        for (int p = 0; p < 2; p++) {                    // B: 128 rows
            int r = lrow + p * 64;
            cp16(base + 9216 + r * 36 + lc4, Bp + (size_t)r * ldb + k0 + lc4);
        }
        CP_COMMIT;
    };

    ISSUE(0);
    for (int i = 0; i < nk; i++) {
        CP_WAIT0;
        __syncthreads();
        if (i + 1 < nk) ISSUE(i + 1);
        const unsigned* As = sm + (i & 1) * 13824;
        const unsigned* Bs = As + 9216;
        #pragma unroll
        for (int h = 0; h < 2; h++) {
            uint4 a0[4], a1[4];
            #pragma unroll
            for (int mi = 0; mi < 4; mi++) {
                int r = wm + mi * 16 + grp;
                a0[mi] = *(const uint4*)(As + r * 36 + tig * 8 + 4 * h);
                a1[mi] = *(const uint4*)(As + (r + 8) * 36 + tig * 8 + 4 * h);
            }
            #pragma unroll
            for (int ni = 0; ni < 4; ni++) {
                int nb = wn + ni * 8 + grp;
                uint4 bf = *(const uint4*)(Bs + nb * 36 + tig * 8 + 4 * h);
                #pragma unroll
                for (int mi = 0; mi < 4; mi++) {
                    mma_tf32(acc[mi][ni], a0[mi].x, a1[mi].x, a0[mi].y, a1[mi].y, bf.x, bf.y);
                    mma_tf32(acc[mi][ni], a0[mi].z, a1[mi].z, a0[mi].w, a1[mi].w, bf.z, bf.w);
                }
            }
        }
    }

    #pragma unroll
    for (int mi = 0; mi < 4; mi++) {
        int row = blockIdx.y * 256 + wm + mi * 16 + grp;
        #pragma unroll
        for (int ni = 0; ni < 4; ni++) {
            int colg = blockIdx.x * 128 + wn + ni * 8 + 2 * tig;   // phys col
            float* Cp;
            int col;
            if (SPLIT) {
                int qsel = blockIdx.x / 6;
                Cp = C + (size_t)qsel * MOFF;
                col = colg - qsel * 768;
            } else {
                Cp = C;
                col = colg;
            }
            float b0 = 0.f, b1 = 0.f;
            if (BIAS) { b0 = bias[colg]; b1 = bias[colg + 1]; }
            float v0 = acc[mi][ni][0] + b0;
            float v1 = acc[mi][ni][1] + b1;
            float v2 = acc[mi][ni][2] + b0;
            float v3 = acc[mi][ni][3] + b1;
            if (RELU)  { v0 = fmaxf(v0, 0.f); v1 = fmaxf(v1, 0.f); v2 = fmaxf(v2, 0.f); v3 = fmaxf(v3, 0.f); }
            if (ROUND) { v0 = f2tf32f(v0); v1 = f2tf32f(v1); v2 = f2tf32f(v2); v3 = f2tf32f(v3); }
            *(float2*)(Cp + (size_t)row * ldc + col)       = make_float2(v0, v1);
            *(float2*)(Cp + (size_t)(row + 8) * ldc + col) = make_float2(v2, v3);
        }
    }
}

// ============ Flash attention (R12-proven: Ps aliases Qs, 2 CTAs/SM) ============
#define FL_SMEM (18432 * 4)
__global__ __launch_bounds__(256, 2) void flash_attn(
    const float* __restrict__ Qg, const float* __restrict__ Kg,
    const float* __restrict__ Vg, float* __restrict__ Og)
{
    extern __shared__ unsigned sm[];
    unsigned* Qs = sm;                      // [2][128*36]  (dead after qf load)
    unsigned* Ps = sm;                      // [2][128*36]  (aliases Qs)
    unsigned* Ks = sm + 2 * 128 * 36;       // [2][64*36]
    unsigned* Vs = Ks + 2 * 64 * 36;        // [2][64*36]

    const int bh = blockIdx.y;
    const int qbase = blockIdx.x * 128;
    const unsigned* Qp = (const unsigned*)(Qg + (size_t)bh * Ss * HDh + (size_t)qbase * HDh);
    const unsigned* Kp = (const unsigned*)(Kg + (size_t)bh * Ss * HDh);
    const unsigned* Vp = (const unsigned*)(Vg + (size_t)bh * Ss * HDh);

    const int tid = threadIdx.x, lane = tid & 31, warp = tid >> 5;
    const int grp = lane >> 2, tig = lane & 3;
    const int wq = warp * 16;

    #pragma unroll
    for (int p = 0; p < 8; p++) {
        int i = tid + p * 256;
        int row = i >> 4, f = i & 15;
        uint4 v = *(const uint4*)(Qp + (size_t)row * 64 + f * 4);
        *(uint4*)(Qs + (f >> 3) * 128 * 36 + row * 36 + (f & 7) * 4) = v;
    }
    __syncthreads();

    uint4 qf[2][2][2];
    #pragma unroll
    for (int s = 0; s < 2; s++) {
        const unsigned* q = Qs + s * 128 * 36;
        #pragma unroll
        for (int rh = 0; rh < 2; rh++) {
            int r = wq + grp + rh * 8;
            qf[s][rh][0] = *(const uint4*)(q + r * 36 + tig * 8);
            qf[s][rh][1] = *(const uint4*)(q + r * 36 + tig * 8 + 4);
        }
    }

    float oa[8][4];
    #pragma unroll
    for (int ni = 0; ni < 8; ni++) { oa[ni][0]=0.f; oa[ni][1]=0.f; oa[ni][2]=0.f; oa[ni][3]=0.f; }
    float m0 = -1e30f, m1 = -1e30f, l0 = 0.f, l1 = 0.f;

    for (int kv0 = 0; kv0 < Ss; kv0 += 64) {
        __syncthreads();
        #pragma unroll
        for (int p = 0; p < 4; p++) {
            int i = tid + p * 256;
            int row = i >> 4, f = i & 15;
            uint4 v = *(const uint4*)(Kp + (size_t)(kv0 + row) * 64 + f * 4);
            *(uint4*)(Ks + (f >> 3) * 64 * 36 + row * 36 + (f & 7) * 4) = v;
        }
        {
            int c = tid >> 6;
            int n = tid & 63;
            #pragma unroll
            for (int s = 0; s < 2; s++) {
                unsigned vb[8];
                #pragma unroll
                for (int t = 0; t < 8; t++)
                    vb[t] = Vp[(size_t)(kv0 + s * 32 + c + 4 * t) * 64 + n];
                unsigned* dst = Vs + s * 64 * 36 + n * 36 + c * 8;
                *(uint4*)(dst)     = make_uint4(vb[0], vb[1], vb[2], vb[3]);
                *(uint4*)(dst + 4) = make_uint4(vb[4], vb[5], vb[6], vb[7]);
            }
        }
        __syncthreads();

        float sacc[8][4];
        #pragma unroll
        for (int ni = 0; ni < 8; ni++) { sacc[ni][0]=0.f; sacc[ni][1]=0.f; sacc[ni][2]=0.f; sacc[ni][3]=0.f; }
        #pragma unroll
        for (int s = 0; s < 2; s++) {
            const unsigned* kb = Ks + s * 64 * 36;
            #pragma unroll
            for (int h = 0; h < 2; h++) {
                #pragma unroll
                for (int ni = 0; ni < 8; ni++) {
                    int nb = ni * 8 + grp;
                    uint4 bf = *(const uint4*)(kb + nb * 36 + tig * 8 + 4 * h);
                    mma_tf32(sacc[ni], qf[s][0][h].x, qf[s][1][h].x, qf[s][0][h].y, qf[s][1][h].y, bf.x, bf.y);
                    mma_tf32(sacc[ni], qf[s][0][h].z, qf[s][1][h].z, qf[s][0][h].w, qf[s][1][h].w, bf.z, bf.w);
                }
            }
        }

        float mx0 = -1e30f, mx1 = -1e30f;
        #pragma unroll
        for (int ni = 0; ni < 8; ni++) {
            sacc[ni][0] *= 0.125f; sacc[ni][1] *= 0.125f; sacc[ni][2] *= 0.125f; sacc[ni][3] *= 0.125f;
            mx0 = fmaxf(mx0, fmaxf(sacc[ni][0], sacc[ni][1]));
            mx1 = fmaxf(mx1, fmaxf(sacc[ni][2], sacc[ni][3]));
        }
        mx0 = fmaxf(mx0, __shfl_xor_sync(0xffffffffu, mx0, 1));
        mx0 = fmaxf(mx0, __shfl_xor_sync(0xffffffffu, mx0, 2));
        mx1 = fmaxf(mx1, __shfl_xor_sync(0xffffffffu, mx1, 1));
        mx1 = fmaxf(mx1, __shfl_xor_sync(0xffffffffu, mx1, 2));
        float mn0 = fmaxf(m0, mx0), mn1 = fmaxf(m1, mx1);
        float al0 = __expf(m0 - mn0), al1 = __expf(m1 - mn1);
        float sum0 = 0.f, sum1 = 0.f;
        {
            int r0 = wq + grp, r1 = r0 + 8;
            #pragma unroll
            for (int ni = 0; ni < 8; ni++) {
                float p0 = __expf(sacc[ni][0] - mn0);
                float p1 = __expf(sacc[ni][1] - mn0);
                float p2 = __expf(sacc[ni][2] - mn1);
                float p3 = __expf(sacc[ni][3] - mn1);
                sum0 += p0 + p1; sum1 += p2 + p3;
                int j  = ni * 8 + 2 * tig;
                int sub = j >> 5, jj = j & 31;
                unsigned* pp = Ps + sub * 128 * 36;
                int s0 = (jj & 3) * 8 + (jj >> 2);
                int s1 = ((jj + 1) & 3) * 8 + ((jj + 1) >> 2);
                pp[r0 * 36 + s0] = f2tf32u(p0);
                pp[r0 * 36 + s1] = f2tf32u(p1);
                pp[r1 * 36 + s0] = f2tf32u(p2);
                pp[r1 * 36 + s1] = f2tf32u(p3);
            }
        }
        sum0 += __shfl_xor_sync(0xffffffffu, sum0, 1);
        sum0 += __shfl_xor_sync(0xffffffffu, sum0, 2);
        sum1 += __shfl_xor_sync(0xffffffffu, sum1, 1);
        sum1 += __shfl_xor_sync(0xffffffffu, sum1, 2);
        l0 = l0 * al0 + sum0;  l1 = l1 * al1 + sum1;
        m0 = mn0;  m1 = mn1;
        #pragma unroll
        for (int ni = 0; ni < 8; ni++) {
            oa[ni][0] *= al0; oa[ni][1] *= al0; oa[ni][2] *= al1; oa[ni][3] *= al1;
        }
        __syncwarp();

        uint4 pf[2][2][2];
        #pragma unroll
        for (int s = 0; s < 2; s++) {
            const unsigned* p = Ps + s * 128 * 36;
            #pragma unroll
            for (int rh = 0; rh < 2; rh++) {
                int r = wq + grp + rh * 8;
                pf[s][rh][0] = *(const uint4*)(p + r * 36 + tig * 8);
                pf[s][rh][1] = *(const uint4*)(p + r * 36 + tig * 8 + 4);
            }
        }
        #pragma unroll
        for (int s = 0; s < 2; s++) {
            const unsigned* vbp = Vs + s * 64 * 36;
            #pragma unroll
            for (int h = 0; h < 2; h++) {
                #pragma unroll
                for (int ni = 0; ni < 8; ni++) {
                    int nb = ni * 8 + grp;
                    uint4 bf = *(const uint4*)(vbp + nb * 36 + tig * 8 + 4 * h);
                    mma_tf32(oa[ni], pf[s][0][h].x, pf[s][1][h].x, pf[s][0][h].y, pf[s][1][h].y, bf.x, bf.y);
                    mma_tf32(oa[ni], pf[s][0][h].z, pf[s][1][h].z, pf[s][0][h].w, pf[s][1][h].w, bf.z, bf.w);
                }
            }
        }
    }

    float i0 = 1.f / l0, i1 = 1.f / l1;
    const int b = bh / Hh, h = bh % Hh;
    float* Op = Og + (size_t)b * Ss * Dd + (size_t)qbase * Dd + h * HDh;
    int r0 = wq + grp;
    #pragma unroll
    for (int ni = 0; ni < 8; ni++) {
        int col = ni * 8 + 2 * tig;
        *(float2*)(Op + (size_t)r0 * Dd + col)       = make_float2(oa[ni][0] * i0, oa[ni][1] * i0);
        *(float2*)(Op + (size_t)(r0 + 8) * Dd + col) = make_float2(oa[ni][2] * i1, oa[ni][3] * i1);
    }
}

// ---------------- add + layernorm: warp-per-row ----------------
__global__ __launch_bounds__(256) void add_ln_kernel(
    const float* __restrict__ x, const float* __restrict__ h,
    const float* __restrict__ g, const float* __restrict__ bias,
    float* __restrict__ out, float* __restrict__ outr, int unperm)
{
    const int lane = threadIdx.x & 31, warp = threadIdx.x >> 5;
    const size_t row = (size_t)blockIdx.x * 8 + warp;
    const float4* px = (const float4*)(x + row * Dd);
    const float4* ph = (const float4*)(h + row * Dd);
    const float4* pg = (const float4*)g;
    const float4* pb = (const float4*)bias;

    float4 v[6];
    float s = 0.f;
    #pragma unroll
    for (int j = 0; j < 6; j++) {
        int i4 = lane + j * 32;
        float4 a = px[i4], b = ph[i4];
        v[j] = make_float4(a.x + b.x, a.y + b.y, a.z + b.z, a.w + b.w);
        s += v[j].x + v[j].y + v[j].z + v[j].w;
    }
    #pragma unroll
    for (int o = 16; o > 0; o >>= 1) s += __shfl_xor_sync(0xffffffffu, s, o);
    float mu = s * (1.f / Dd);

    float q = 0.f;
    #pragma unroll
    for (int j = 0; j < 6; j++) {
        float dx = v[j].x - mu, dy = v[j].y - mu, dz = v[j].z - mu, dw = v[j].w - mu;
        q += dx * dx + dy * dy + dz * dz + dw * dw;
    }
    #pragma unroll
    for (int o = 16; o > 0; o >>= 1) q += __shfl_xor_sync(0xffffffffu, q, o);
    float inv = rsqrtf(q * (1.f / Dd) + 1e-5f);

    float* po = out + row * Dd;
    float* pr = outr ? outr + row * Dd : nullptr;
    #pragma unroll
    for (int j = 0; j < 6; j++) {
        int i4 = lane + j * 32;
        float4 gg = pg[i4], bb = pb[i4];
        float o0 = (v[j].x - mu) * inv * gg.x + bb.x;
        float o1 = (v[j].y - mu) * inv * gg.y + bb.y;
        float o2 = (v[j].z - mu) * inv * gg.z + bb.z;
        float o3 = (v[j].w - mu) * inv * gg.w + bb.w;
        if (unperm) {
            int c = i4 * 4;
            po[(c & ~31) | inv32(c & 31)]             = o0;
            po[((c+1) & ~31) | inv32((c+1) & 31)]     = o1;
            po[((c+2) & ~31) | inv32((c+2) & 31)]     = o2;
            po[((c+3) & ~31) | inv32((c+3) & 31)]     = o3;
        } else {
            ((float4*)po)[i4] = make_float4(o0, o1, o2, o3);
        }
        if (pr)
            ((float4*)pr)[i4] = make_float4(f2tf32f(o0), f2tf32f(o1), f2tf32f(o2), f2tf32f(o3));
    }
}

// ---------------- host launcher ----------------
extern "C" void kernel_launch(void* const* d_in, const int* in_sizes, int n_in,
                              void* d_out, int out_size) {
    const int*   ids  = (const int*)  d_in[0];
    const float* emb  = (const float*)d_in[1];
    const float* pe   = (const float*)d_in[2];
    const float* Wq   = (const float*)d_in[3];
    const float* bq   = (const float*)d_in[4];
    const float* Wk   = (const float*)d_in[5];
    const float* bk   = (const float*)d_in[6];
    const float* Wv   = (const float*)d_in[7];
    const float* bv   = (const float*)d_in[8];
    const float* W1   = (const float*)d_in[9];
    const float* b1   = (const float*)d_in[10];
    const float* W2   = (const float*)d_in[11];
    const float* b2   = (const float*)d_in[12];
    const float* ln1g = (const float*)d_in[13];
    const float* ln1b = (const float*)d_in[14];
    const float* ln2g = (const float*)d_in[15];
    const float* ln2b = (const float*)d_in[16];

    float *X, *Xr, *QKV, *Hb, *Y1, *Y1r, *F, *Wqkv, *Bqkv, *W1r, *W2r;
    float *B1p, *B2p, *L1g, *L1b, *L2g, *L2b;
    cudaGetSymbolAddress((void**)&X,    gX);
    cudaGetSymbolAddress((void**)&Xr,   gXr);
    cudaGetSymbolAddress((void**)&QKV,  gQKV);
    cudaGetSymbolAddress((void**)&Hb,   gHb);
    cudaGetSymbolAddress((void**)&Y1,   gY1);
    cudaGetSymbolAddress((void**)&Y1r,  gY1r);
    cudaGetSymbolAddress((void**)&F,    gF);
    cudaGetSymbolAddress((void**)&Wqkv, gWqkv);
    cudaGetSymbolAddress((void**)&Bqkv, gBqkv);
    cudaGetSymbolAddress((void**)&W1r,  gW1r);
    cudaGetSymbolAddress((void**)&W2r,  gW2r);
    cudaGetSymbolAddress((void**)&B1p,  gB1p);
    cudaGetSymbolAddress((void**)&B2p,  gB2p);
    cudaGetSymbolAddress((void**)&L1g,  gLn1g);
    cudaGetSymbolAddress((void**)&L1b,  gLn1b);
    cudaGetSymbolAddress((void**)&L2g,  gLn2g);
    cudaGetSymbolAddress((void**)&L2b,  gLn2b);

    const int NT_SMEM = 2 * 13824 * 4;   // 110592 B (256x128 tile, 2 stages)
    cudaFuncSetAttribute(gemm_tf32_nt<true,  false, true,  true >, cudaFuncAttributeMaxDynamicSharedMemorySize, NT_SMEM);
    cudaFuncSetAttribute(gemm_tf32_nt<true,  true,  true,  false>, cudaFuncAttributeMaxDynamicSharedMemorySize, NT_SMEM);
    cudaFuncSetAttribute(gemm_tf32_nt<true,  false, false, false>, cudaFuncAttributeMaxDynamicSharedMemorySize, NT_SMEM);
    cudaFuncSetAttribute(flash_attn, cudaFuncAttributeMaxDynamicSharedMemorySize, FL_SMEM);

    const int M = Bb * Ss;   // 8192

    // prep: permute+round weights, permute biases/params
    perm_weight<<<dim3(768, LL), 256>>>(Wqkv,            Wq, 768, 2304L*768, 768L*768);
    perm_weight<<<dim3(768, LL), 256>>>(Wqkv + 768*768,  Wk, 768, 2304L*768, 768L*768);
    perm_weight<<<dim3(768, LL), 256>>>(Wqkv + 1536*768, Wv, 768, 2304L*768, 768L*768);
    perm_weight<<<dim3(DFF, LL), 256>>>(W1r,             W1, 768, (long)DFF*768, (long)DFF*768);
    perm_weight<<<dim3(768, LL), 256>>>(W2r,             W2, DFF, 768L*DFF, 768L*DFF);
    pack_qkv_b<<<(LL * 2304) / 256, 256>>>(Bqkv, bq, bk, bv);
    perm_vec<<<(LL * DFF) / 256, 256>>>(B1p, b1);
    perm_vec<<<(LL * Dd)  / 256, 256>>>(B2p, b2);
    perm_vec<<<(LL * Dd)  / 256, 256>>>(L1g, ln1g);
    perm_vec<<<(LL * Dd)  / 256, 256>>>(L1b, ln1b);
    perm_vec<<<(LL * Dd)  / 256, 256>>>(L2g, ln2g);
    perm_vec<<<(LL * Dd)  / 256, 256>>>(L2b, ln2b);

    embed_kernel<<<(Bb * Ss * Dd) / 256, 256>>>(ids, emb, pe, X, Xr);

    for (int l = 0; l < LL; l++) {
        gemm_tf32_nt<true, false, true, true><<<dim3(18, M / 256), 512, NT_SMEM>>>(
            M, 3 * Dd, Dd, Xr, Dd, Wqkv + (size_t)l * 3 * Dd * Dd, Dd,
            QKV, Dd, Bqkv + (size_t)l * 3 * Dd);

        flash_attn<<<dim3(Ss / 128, Bb * Hh), 256, FL_SMEM>>>(
            QKV, QKV + MOFF, QKV + 2 * MOFF, Hb);

        add_ln_kernel<<<M / 8, 256>>>(X, Hb, L1g + l * Dd, L1b + l * Dd, Y1, Y1r, 0);

        gemm_tf32_nt<true, true, true, false><<<dim3(DFF / 128, M / 256), 512, NT_SMEM>>>(
            M, DFF, Dd, Y1r, Dd, W1r + (size_t)l * DFF * Dd, Dd, F, DFF, B1p + l * DFF);
        gemm_tf32_nt<true, false, false, false><<<dim3(Dd / 128, M / 256), 512, NT_SMEM>>>(
            M, Dd, DFF, F, DFF, W2r + (size_t)l * Dd * DFF, DFF, Hb, Dd, B2p + l * Dd);

        float* outp = (l == LL - 1) ? (float*)d_out : X;
        float* outr = (l == LL - 1) ? nullptr : Xr;
        add_ln_kernel<<<M / 8, 256>>>(Y1, Hb, L2g + l * Dd, L2b + l * Dd, outp, outr, (l == LL - 1) ? 1 : 0);
    }
}

// round 14
// speedup vs baseline: 1.1272x; 1.1272x over previous
#include <cuda_runtime.h>
#include <cstdint>
#include <stdint.h>
#include <math.h>

#define Bb   8
#define Ss   1024
#define Dd   768
#define Hh   12
#define HDh  64
#define DFF  3072
#define LL   6
#define MOFF (Bb*Ss*Dd)      // 6291456, size of one of Q/K/V

// ---------------- scratch ("P-layout": within each 32-aligned feature block,
// logical k stored at (k&3)*8 + (k>>2)) ----------------
__device__ float gX   [Bb*Ss*Dd];
__device__ float gXr  [Bb*Ss*Dd];
__device__ float gQKV [3*Bb*Ss*Dd];
__device__ float gHb  [Bb*Ss*Dd];
__device__ float gY1  [Bb*Ss*Dd];
__device__ float gY1r [Bb*Ss*Dd];
__device__ float gF   [Bb*Ss*DFF];
__device__ float gWqkv[LL*3*Dd*Dd];
__device__ float gBqkv[LL*3*Dd];
__device__ float gW1r [LL*DFF*Dd];
__device__ float gW2r [LL*Dd*DFF];
__device__ float gB1p [LL*DFF];
__device__ float gB2p [LL*Dd];
__device__ float gLn1g[LL*Dd];
__device__ float gLn1b[LL*Dd];
__device__ float gLn2g[LL*Dd];
__device__ float gLn2b[LL*Dd];

// ---------------- helpers ----------------
__device__ __forceinline__ int inv32(int j) { return ((j & 7) << 2) | (j >> 3); }

__device__ __forceinline__ float f2tf32f(float f) {
    unsigned u;
    asm("cvt.rna.tf32.f32 %0, %1;" : "=r"(u) : "f"(f));
    return __uint_as_float(u);
}
__device__ __forceinline__ unsigned f2tf32u(float f) {
    unsigned u;
    asm("cvt.rna.tf32.f32 %0, %1;" : "=r"(u) : "f"(f));
    return u;
}

__device__ __forceinline__ void mma_tf32(float c[4], unsigned a0, unsigned a1, unsigned a2, unsigned a3,
                                         unsigned b0, unsigned b1) {
    asm volatile(
        "mma.sync.aligned.m16n8k8.row.col.f32.tf32.tf32.f32 "
        "{%0,%1,%2,%3}, {%4,%5,%6,%7}, {%8,%9}, {%0,%1,%2,%3};\n"
        : "+f"(c[0]), "+f"(c[1]), "+f"(c[2]), "+f"(c[3])
        : "r"(a0), "r"(a1), "r"(a2), "r"(a3), "r"(b0), "r"(b1));
}

__device__ __forceinline__ void cp16(unsigned* smem_dst, const void* gmem_src) {
    unsigned s = (unsigned)__cvta_generic_to_shared(smem_dst);
    asm volatile("cp.async.cg.shared.global [%0], [%1], 16;\n" :: "r"(s), "l"(gmem_src));
}
#define CP_COMMIT asm volatile("cp.async.commit_group;\n" ::)
#define CP_WAIT0  asm volatile("cp.async.wait_group 0;\n" ::)

// ---------------- fused prep: ALL weight/param permute+round in ONE launch ----------------
// Region map over blockIdx.x (256 threads each):
//   [0, 13824)          : Wqkv rows   (LL*2304 rows, 768 cols)
//   [13824, 32256)      : W1 rows     (LL*3072 rows, 768 cols)
//   [32256, 36864)      : W2 rows     (LL*768 rows, 3072 cols)
//   [36864, 36864+216)  : vectors     (55296 elements)
__global__ void fused_prep(
    const float* __restrict__ Wq, const float* __restrict__ Wk, const float* __restrict__ Wv,
    const float* __restrict__ W1, const float* __restrict__ W2,
    const float* __restrict__ bq, const float* __restrict__ bk, const float* __restrict__ bv,
    const float* __restrict__ b1, const float* __restrict__ b2,
    const float* __restrict__ ln1g, const float* __restrict__ ln1b,
    const float* __restrict__ ln2g, const float* __restrict__ ln2b)
{
    const int b = blockIdx.x;
    if (b < 13824) {                     // Wqkv: packed [L][2304][768]
        int l = b / 2304, rp = b % 2304;
        int r = (rp & ~31) | inv32(rp & 31);      // matrix boundaries are 768-aligned (mult of 32)
        const float* src = (r < 768)  ? Wq + ((size_t)l * 768 + r) * 768
                         : (r < 1536) ? Wk + ((size_t)l * 768 + (r - 768)) * 768
                                      : Wv + ((size_t)l * 768 + (r - 1536)) * 768;
        float* d = gWqkv + ((size_t)l * 2304 + rp) * 768;
        for (int cp = threadIdx.x; cp < 768; cp += 256) {
            int c = (cp & ~31) | inv32(cp & 31);
            d[cp] = f2tf32f(src[c]);
        }
    } else if (b < 32256) {              // W1: [L][3072][768]
        int i = b - 13824;
        int l = i / 3072, rp = i % 3072;
        int r = (rp & ~31) | inv32(rp & 31);
        const float* src = W1 + ((size_t)l * 3072 + r) * 768;
        float* d = gW1r + ((size_t)l * 3072 + rp) * 768;
        for (int cp = threadIdx.x; cp < 768; cp += 256) {
            int c = (cp & ~31) | inv32(cp & 31);
            d[cp] = f2tf32f(src[c]);
        }
    } else if (b < 36864) {              // W2: [L][768][3072]
        int i = b - 32256;
        int l = i / 768, rp = i % 768;
        int r = (rp & ~31) | inv32(rp & 31);
        const float* src = W2 + ((size_t)l * 768 + r) * 3072;
        float* d = gW2r + ((size_t)l * 768 + rp) * 3072;
        for (int cp = threadIdx.x; cp < 3072; cp += 256) {
            int c = (cp & ~31) | inv32(cp & 31);
            d[cp] = f2tf32f(src[c]);
        }
    } else {                             // vectors: 55296 elements
        int i = (b - 36864) * 256 + threadIdx.x;
        if (i < 13824) {                 // Bqkv (perm + pack)
            int pos = (i & ~31) | inv32(i & 31);
            int l = pos / 2304, n = pos % 2304;
            gBqkv[i] = (n < 768) ? bq[l * 768 + n]
                     : (n < 1536) ? bk[l * 768 + n - 768]
                                  : bv[l * 768 + n - 1536];
        } else if (i < 32256) {          // B1p
            int j = i - 13824;
            gB1p[j] = b1[(j & ~31) | inv32(j & 31)];
        } else if (i < 36864) {          // B2p
            int j = i - 32256;
            gB2p[j] = b2[(j & ~31) | inv32(j & 31)];
        } else if (i < 41472) {          // L1g
            int j = i - 36864;
            gLn1g[j] = ln1g[(j & ~31) | inv32(j & 31)];
        } else if (i < 46080) {          // L1b
            int j = i - 41472;
            gLn1b[j] = ln1b[(j & ~31) | inv32(j & 31)];
        } else if (i < 50688) {          // L2g
            int j = i - 46080;
            gLn2g[j] = ln2g[(j & ~31) | inv32(j & 31)];
        } else if (i < 55296) {          // L2b
            int j = i - 50688;
            gLn2b[j] = ln2b[(j & ~31) | inv32(j & 31)];
        }
    }
}

// ---------------- embedding (writes P-layout) ----------------
__global__ void embed_kernel(const int* __restrict__ ids, const float* __restrict__ emb,
                             const float* __restrict__ pe, float* __restrict__ x,
                             float* __restrict__ xr) {
    int i  = blockIdx.x * blockDim.x + threadIdx.x;
    int dp = i % Dd;
    int bs = i / Dd;
    int s  = bs % Ss;
    int d  = (dp & ~31) | inv32(dp & 31);
    float v = emb[(size_t)ids[bs] * Dd + d] + pe[(size_t)s * Dd + d];
    x[i]  = v;
    xr[i] = f2tf32f(v);
}

// ============ TF32 NT GEMM (R12-proven): cp.async double-buffered, BM=128,BN=128,BK=32,
// 256 threads, 2 CTA/SM, ONE barrier per k-tile ============
template<bool BIAS, bool RELU, bool ROUND, bool SPLIT>
__global__ __launch_bounds__(256, 2) void gemm_tf32_nt(
    int M, int N, int K,
    const float* __restrict__ A, int lda,
    const float* __restrict__ B, int ldb,
    float* __restrict__ C, int ldc,
    const float* __restrict__ bias)
{
    extern __shared__ unsigned sm[];
    const unsigned* Ap = (const unsigned*)(A + (size_t)(blockIdx.y * 128) * lda);
    const unsigned* Bp = (const unsigned*)(B + (size_t)(blockIdx.x * 128) * ldb);
    const int tid = threadIdx.x;
    const int lane = tid & 31, warp = tid >> 5;
    const int wm = (warp >> 2) * 64, wn = (warp & 3) * 32;
    const int grp = lane >> 2, tig = lane & 3;
    const int lrow = tid >> 3;            // 0..31
    const int lc4  = (tid & 7) * 4;       // 0..28

    float acc[4][4][4] = {};
    const int nk = K >> 5;

    auto ISSUE = [&](int i) {
        int k0 = i << 5;
        unsigned* base = sm + (i & 1) * 9216;
        #pragma unroll
        for (int p = 0; p < 4; p++) {
            int r = lrow + p * 32;
            cp16(base + r * 36 + lc4,        Ap + (size_t)r * lda + k0 + lc4);
            cp16(base + 4608 + r * 36 + lc4, Bp + (size_t)r * ldb + k0 + lc4);
        }
        CP_COMMIT;
    };

    ISSUE(0);
    for (int i = 0; i < nk; i++) {
        CP_WAIT0;
        __syncthreads();
        if (i + 1 < nk) ISSUE(i + 1);
        const unsigned* As = sm + (i & 1) * 9216;
        const unsigned* Bs = As + 4608;
        #pragma unroll
        for (int h = 0; h < 2; h++) {
            uint4 a0[4], a1[4];
            #pragma unroll
            for (int mi = 0; mi < 4; mi++) {
                int r = wm + mi * 16 + grp;
                a0[mi] = *(const uint4*)(As + r * 36 + tig * 8 + 4 * h);
                a1[mi] = *(const uint4*)(As + (r + 8) * 36 + tig * 8 + 4 * h);
            }
            #pragma unroll
            for (int ni = 0; ni < 4; ni++) {
                int nb = wn + ni * 8 + grp;
                uint4 bf = *(const uint4*)(Bs + nb * 36 + tig * 8 + 4 * h);
                #pragma unroll
                for (int mi = 0; mi < 4; mi++) {
                    mma_tf32(acc[mi][ni], a0[mi].x, a1[mi].x, a0[mi].y, a1[mi].y, bf.x, bf.y);
                    mma_tf32(acc[mi][ni], a0[mi].z, a1[mi].z, a0[mi].w, a1[mi].w, bf.z, bf.w);
                }
            }
        }
    }

    #pragma unroll
    for (int mi = 0; mi < 4; mi++) {
        int row = blockIdx.y * 128 + wm + mi * 16 + grp;
        #pragma unroll
        for (int ni = 0; ni < 4; ni++) {
            int colg = blockIdx.x * 128 + wn + ni * 8 + 2 * tig;   // phys col
            float* Cp;
            int col;
            if (SPLIT) {
                int qsel = blockIdx.x / 6;
                Cp = C + (size_t)qsel * MOFF;
                col = colg - qsel * 768;
            } else {
                Cp = C;
                col = colg;
            }
            float b0 = 0.f, b1 = 0.f;
            if (BIAS) { b0 = bias[colg]; b1 = bias[colg + 1]; }
            float v0 = acc[mi][ni][0] + b0;
            float v1 = acc[mi][ni][1] + b1;
            float v2 = acc[mi][ni][2] + b0;
            float v3 = acc[mi][ni][3] + b1;
            if (RELU)  { v0 = fmaxf(v0, 0.f); v1 = fmaxf(v1, 0.f); v2 = fmaxf(v2, 0.f); v3 = fmaxf(v3, 0.f); }
            if (ROUND) { v0 = f2tf32f(v0); v1 = f2tf32f(v1); v2 = f2tf32f(v2); v3 = f2tf32f(v3); }
            *(float2*)(Cp + (size_t)row * ldc + col)       = make_float2(v0, v1);
            *(float2*)(Cp + (size_t)(row + 8) * ldc + col) = make_float2(v2, v3);
        }
    }
}

// ============ Flash attention (R12-proven: Ps aliases Qs, 2 CTAs/SM) ============
#define FL_SMEM (18432 * 4)
__global__ __launch_bounds__(256, 2) void flash_attn(
    const float* __restrict__ Qg, const float* __restrict__ Kg,
    const float* __restrict__ Vg, float* __restrict__ Og)
{
    extern __shared__ unsigned sm[];
    unsigned* Qs = sm;                      // [2][128*36]  (dead after qf load)
    unsigned* Ps = sm;                      // [2][128*36]  (aliases Qs)
    unsigned* Ks = sm + 2 * 128 * 36;       // [2][64*36]
    unsigned* Vs = Ks + 2 * 64 * 36;        // [2][64*36]

    const int bh = blockIdx.y;
    const int qbase = blockIdx.x * 128;
    const unsigned* Qp = (const unsigned*)(Qg + (size_t)bh * Ss * HDh + (size_t)qbase * HDh);
    const unsigned* Kp = (const unsigned*)(Kg + (size_t)bh * Ss * HDh);
    const unsigned* Vp = (const unsigned*)(Vg + (size_t)bh * Ss * HDh);

    const int tid = threadIdx.x, lane = tid & 31, warp = tid >> 5;
    const int grp = lane >> 2, tig = lane & 3;
    const int wq = warp * 16;

    #pragma unroll
    for (int p = 0; p < 8; p++) {
        int i = tid + p * 256;
        int row = i >> 4, f = i & 15;
        uint4 v = *(const uint4*)(Qp + (size_t)row * 64 + f * 4);
        *(uint4*)(Qs + (f >> 3) * 128 * 36 + row * 36 + (f & 7) * 4) = v;
    }
    __syncthreads();

    uint4 qf[2][2][2];
    #pragma unroll
    for (int s = 0; s < 2; s++) {
        const unsigned* q = Qs + s * 128 * 36;
        #pragma unroll
        for (int rh = 0; rh < 2; rh++) {
            int r = wq + grp + rh * 8;
            qf[s][rh][0] = *(const uint4*)(q + r * 36 + tig * 8);
            qf[s][rh][1] = *(const uint4*)(q + r * 36 + tig * 8 + 4);
        }
    }

    float oa[8][4];
    #pragma unroll
    for (int ni = 0; ni < 8; ni++) { oa[ni][0]=0.f; oa[ni][1]=0.f; oa[ni][2]=0.f; oa[ni][3]=0.f; }
    float m0 = -1e30f, m1 = -1e30f, l0 = 0.f, l1 = 0.f;

    for (int kv0 = 0; kv0 < Ss; kv0 += 64) {
        __syncthreads();
        #pragma unroll
        for (int p = 0; p < 4; p++) {
            int i = tid + p * 256;
            int row = i >> 4, f = i & 15;
            uint4 v = *(const uint4*)(Kp + (size_t)(kv0 + row) * 64 + f * 4);
            *(uint4*)(Ks + (f >> 3) * 64 * 36 + row * 36 + (f & 7) * 4) = v;
        }
        {
            int c = tid >> 6;
            int n = tid & 63;
            #pragma unroll
            for (int s = 0; s < 2; s++) {
                unsigned vb[8];
                #pragma unroll
                for (int t = 0; t < 8; t++)
                    vb[t] = Vp[(size_t)(kv0 + s * 32 + c + 4 * t) * 64 + n];
                unsigned* dst = Vs + s * 64 * 36 + n * 36 + c * 8;
                *(uint4*)(dst)     = make_uint4(vb[0], vb[1], vb[2], vb[3]);
                *(uint4*)(dst + 4) = make_uint4(vb[4], vb[5], vb[6], vb[7]);
            }
        }
        __syncthreads();

        float sacc[8][4];
        #pragma unroll
        for (int ni = 0; ni < 8; ni++) { sacc[ni][0]=0.f; sacc[ni][1]=0.f; sacc[ni][2]=0.f; sacc[ni][3]=0.f; }
        #pragma unroll
        for (int s = 0; s < 2; s++) {
            const unsigned* kb = Ks + s * 64 * 36;
            #pragma unroll
            for (int h = 0; h < 2; h++) {
                #pragma unroll
                for (int ni = 0; ni < 8; ni++) {
                    int nb = ni * 8 + grp;
                    uint4 bf = *(const uint4*)(kb + nb * 36 + tig * 8 + 4 * h);
                    mma_tf32(sacc[ni], qf[s][0][h].x, qf[s][1][h].x, qf[s][0][h].y, qf[s][1][h].y, bf.x, bf.y);
                    mma_tf32(sacc[ni], qf[s][0][h].z, qf[s][1][h].z, qf[s][0][h].w, qf[s][1][h].w, bf.z, bf.w);
                }
            }
        }

        float mx0 = -1e30f, mx1 = -1e30f;
        #pragma unroll
        for (int ni = 0; ni < 8; ni++) {
            sacc[ni][0] *= 0.125f; sacc[ni][1] *= 0.125f; sacc[ni][2] *= 0.125f; sacc[ni][3] *= 0.125f;
            mx0 = fmaxf(mx0, fmaxf(sacc[ni][0], sacc[ni][1]));
            mx1 = fmaxf(mx1, fmaxf(sacc[ni][2], sacc[ni][3]));
        }
        mx0 = fmaxf(mx0, __shfl_xor_sync(0xffffffffu, mx0, 1));
        mx0 = fmaxf(mx0, __shfl_xor_sync(0xffffffffu, mx0, 2));
        mx1 = fmaxf(mx1, __shfl_xor_sync(0xffffffffu, mx1, 1));
        mx1 = fmaxf(mx1, __shfl_xor_sync(0xffffffffu, mx1, 2));
        float mn0 = fmaxf(m0, mx0), mn1 = fmaxf(m1, mx1);
        float al0 = __expf(m0 - mn0), al1 = __expf(m1 - mn1);
        float sum0 = 0.f, sum1 = 0.f;
        {
            int r0 = wq + grp, r1 = r0 + 8;
            #pragma unroll
            for (int ni = 0; ni < 8; ni++) {
                float p0 = __expf(sacc[ni][0] - mn0);
                float p1 = __expf(sacc[ni][1] - mn0);
                float p2 = __expf(sacc[ni][2] - mn1);
                float p3 = __expf(sacc[ni][3] - mn1);
                sum0 += p0 + p1; sum1 += p2 + p3;
                int j  = ni * 8 + 2 * tig;
                int sub = j >> 5, jj = j & 31;
                unsigned* pp = Ps + sub * 128 * 36;
                int s0 = (jj & 3) * 8 + (jj >> 2);
                int s1 = ((jj + 1) & 3) * 8 + ((jj + 1) >> 2);
                pp[r0 * 36 + s0] = f2tf32u(p0);
                pp[r0 * 36 + s1] = f2tf32u(p1);
                pp[r1 * 36 + s0] = f2tf32u(p2);
                pp[r1 * 36 + s1] = f2tf32u(p3);
            }
        }
        sum0 += __shfl_xor_sync(0xffffffffu, sum0, 1);
        sum0 += __shfl_xor_sync(0xffffffffu, sum0, 2);
        sum1 += __shfl_xor_sync(0xffffffffu, sum1, 1);
        sum1 += __shfl_xor_sync(0xffffffffu, sum1, 2);
        l0 = l0 * al0 + sum0;  l1 = l1 * al1 + sum1;
        m0 = mn0;  m1 = mn1;
        #pragma unroll
        for (int ni = 0; ni < 8; ni++) {
            oa[ni][0] *= al0; oa[ni][1] *= al0; oa[ni][2] *= al1; oa[ni][3] *= al1;
        }
        __syncwarp();

        uint4 pf[2][2][2];
        #pragma unroll
        for (int s = 0; s < 2; s++) {
            const unsigned* p = Ps + s * 128 * 36;
            #pragma unroll
            for (int rh = 0; rh < 2; rh++) {
                int r = wq + grp + rh * 8;
                pf[s][rh][0] = *(const uint4*)(p + r * 36 + tig * 8);
                pf[s][rh][1] = *(const uint4*)(p + r * 36 + tig * 8 + 4);
            }
        }
        #pragma unroll
        for (int s = 0; s < 2; s++) {
            const unsigned* vbp = Vs + s * 64 * 36;
            #pragma unroll
            for (int h = 0; h < 2; h++) {
                #pragma unroll
                for (int ni = 0; ni < 8; ni++) {
                    int nb = ni * 8 + grp;
                    uint4 bf = *(const uint4*)(vbp + nb * 36 + tig * 8 + 4 * h);
                    mma_tf32(oa[ni], pf[s][0][h].x, pf[s][1][h].x, pf[s][0][h].y, pf[s][1][h].y, bf.x, bf.y);
                    mma_tf32(oa[ni], pf[s][0][h].z, pf[s][1][h].z, pf[s][0][h].w, pf[s][1][h].w, bf.z, bf.w);
                }
            }
        }
    }

    float i0 = 1.f / l0, i1 = 1.f / l1;
    const int b = bh / Hh, h = bh % Hh;
    float* Op = Og + (size_t)b * Ss * Dd + (size_t)qbase * Dd + h * HDh;
    int r0 = wq + grp;
    #pragma unroll
    for (int ni = 0; ni < 8; ni++) {
        int col = ni * 8 + 2 * tig;
        *(float2*)(Op + (size_t)r0 * Dd + col)       = make_float2(oa[ni][0] * i0, oa[ni][1] * i0);
        *(float2*)(Op + (size_t)(r0 + 8) * Dd + col) = make_float2(oa[ni][2] * i1, oa[ni][3] * i1);
    }
}

// ---------------- add + layernorm: warp-per-row ----------------
__global__ __launch_bounds__(256) void add_ln_kernel(
    const float* __restrict__ x, const float* __restrict__ h,
    const float* __restrict__ g, const float* __restrict__ bias,
    float* __restrict__ out, float* __restrict__ outr, int unperm)
{
    const int lane = threadIdx.x & 31, warp = threadIdx.x >> 5;
    const size_t row = (size_t)blockIdx.x * 8 + warp;
    const float4* px = (const float4*)(x + row * Dd);
    const float4* ph = (const float4*)(h + row * Dd);
    const float4* pg = (const float4*)g;
    const float4* pb = (const float4*)bias;

    float4 v[6];
    float s = 0.f;
    #pragma unroll
    for (int j = 0; j < 6; j++) {
        int i4 = lane + j * 32;
        float4 a = px[i4], b = ph[i4];
        v[j] = make_float4(a.x + b.x, a.y + b.y, a.z + b.z, a.w + b.w);
        s += v[j].x + v[j].y + v[j].z + v[j].w;
    }
    #pragma unroll
    for (int o = 16; o > 0; o >>= 1) s += __shfl_xor_sync(0xffffffffu, s, o);
    float mu = s * (1.f / Dd);

    float q = 0.f;
    #pragma unroll
    for (int j = 0; j < 6; j++) {
        float dx = v[j].x - mu, dy = v[j].y - mu, dz = v[j].z - mu, dw = v[j].w - mu;
        q += dx * dx + dy * dy + dz * dz + dw * dw;
    }
    #pragma unroll
    for (int o = 16; o > 0; o >>= 1) q += __shfl_xor_sync(0xffffffffu, q, o);
    float inv = rsqrtf(q * (1.f / Dd) + 1e-5f);

    float* po = out + row * Dd;
    float* pr = outr ? outr + row * Dd : nullptr;
    #pragma unroll
    for (int j = 0; j < 6; j++) {
        int i4 = lane + j * 32;
        float4 gg = pg[i4], bb = pb[i4];
        float o0 = (v[j].x - mu) * inv * gg.x + bb.x;
        float o1 = (v[j].y - mu) * inv * gg.y + bb.y;
        float o2 = (v[j].z - mu) * inv * gg.z + bb.z;
        float o3 = (v[j].w - mu) * inv * gg.w + bb.w;
        if (unperm) {
            int c = i4 * 4;
            po[(c & ~31) | inv32(c & 31)]             = o0;
            po[((c+1) & ~31) | inv32((c+1) & 31)]     = o1;
            po[((c+2) & ~31) | inv32((c+2) & 31)]     = o2;
            po[((c+3) & ~31) | inv32((c+3) & 31)]     = o3;
        } else {
            ((float4*)po)[i4] = make_float4(o0, o1, o2, o3);
        }
        if (pr)
            ((float4*)pr)[i4] = make_float4(f2tf32f(o0), f2tf32f(o1), f2tf32f(o2), f2tf32f(o3));
    }
}

// ---------------- host launcher ----------------
extern "C" void kernel_launch(void* const* d_in, const int* in_sizes, int n_in,
                              void* d_out, int out_size) {
    const int*   ids  = (const int*)  d_in[0];
    const float* emb  = (const float*)d_in[1];
    const float* pe   = (const float*)d_in[2];
    const float* Wq   = (const float*)d_in[3];
    const float* bq   = (const float*)d_in[4];
    const float* Wk   = (const float*)d_in[5];
    const float* bk   = (const float*)d_in[6];
    const float* Wv   = (const float*)d_in[7];
    const float* bv   = (const float*)d_in[8];
    const float* W1   = (const float*)d_in[9];
    const float* b1   = (const float*)d_in[10];
    const float* W2   = (const float*)d_in[11];
    const float* b2   = (const float*)d_in[12];
    const float* ln1g = (const float*)d_in[13];
    const float* ln1b = (const float*)d_in[14];
    const float* ln2g = (const float*)d_in[15];
    const float* ln2b = (const float*)d_in[16];

    float *X, *Xr, *QKV, *Hb, *Y1, *Y1r, *F, *Wqkv, *Bqkv, *W1r, *W2r;
    float *B1p, *L1g, *L1b, *L2g, *L2b, *B2p;
    cudaGetSymbolAddress((void**)&X,    gX);
    cudaGetSymbolAddress((void**)&Xr,   gXr);
    cudaGetSymbolAddress((void**)&QKV,  gQKV);
    cudaGetSymbolAddress((void**)&Hb,   gHb);
    cudaGetSymbolAddress((void**)&Y1,   gY1);
    cudaGetSymbolAddress((void**)&Y1r,  gY1r);
    cudaGetSymbolAddress((void**)&F,    gF);
    cudaGetSymbolAddress((void**)&Wqkv, gWqkv);
    cudaGetSymbolAddress((void**)&Bqkv, gBqkv);
    cudaGetSymbolAddress((void**)&W1r,  gW1r);
    cudaGetSymbolAddress((void**)&W2r,  gW2r);
    cudaGetSymbolAddress((void**)&B1p,  gB1p);
    cudaGetSymbolAddress((void**)&B2p,  gB2p);
    cudaGetSymbolAddress((void**)&L1g,  gLn1g);
    cudaGetSymbolAddress((void**)&L1b,  gLn1b);
    cudaGetSymbolAddress((void**)&L2g,  gLn2g);
    cudaGetSymbolAddress((void**)&L2b,  gLn2b);

    const int NT_SMEM = 2 * 9216 * 4;   // 73728 B
    cudaFuncSetAttribute(gemm_tf32_nt<true,  false, true,  true >, cudaFuncAttributeMaxDynamicSharedMemorySize, NT_SMEM);
    cudaFuncSetAttribute(gemm_tf32_nt<true,  true,  true,  false>, cudaFuncAttributeMaxDynamicSharedMemorySize, NT_SMEM);
    cudaFuncSetAttribute(gemm_tf32_nt<true,  false, false, false>, cudaFuncAttributeMaxDynamicSharedMemorySize, NT_SMEM);
    cudaFuncSetAttribute(flash_attn, cudaFuncAttributeMaxDynamicSharedMemorySize, FL_SMEM);

    const int M = Bb * Ss;   // 8192

    // launch 1: ALL prep fused (also shifts ncu -s 5 capture onto the FFN1 GEMM)
    fused_prep<<<37080, 256>>>(Wq, Wk, Wv, W1, W2, bq, bk, bv, b1, b2, ln1g, ln1b, ln2g, ln2b);
    // launch 2: embedding
    embed_kernel<<<(Bb * Ss * Dd) / 256, 256>>>(ids, emb, pe, X, Xr);

    for (int l = 0; l < LL; l++) {
        gemm_tf32_nt<true, false, true, true><<<dim3(18, M / 128), 256, NT_SMEM>>>(
            M, 3 * Dd, Dd, Xr, Dd, Wqkv + (size_t)l * 3 * Dd * Dd, Dd,
            QKV, Dd, Bqkv + (size_t)l * 3 * Dd);

        flash_attn<<<dim3(Ss / 128, Bb * Hh), 256, FL_SMEM>>>(
            QKV, QKV + MOFF, QKV + 2 * MOFF, Hb);

        add_ln_kernel<<<M / 8, 256>>>(X, Hb, L1g + l * Dd, L1b + l * Dd, Y1, Y1r, 0);

        gemm_tf32_nt<true, true, true, false><<<dim3(DFF / 128, M / 128), 256, NT_SMEM>>>(
            M, DFF, Dd, Y1r, Dd, W1r + (size_t)l * DFF * Dd, Dd, F, DFF, B1p + l * DFF);
        gemm_tf32_nt<true, false, false, false><<<dim3(Dd / 128, M / 128), 256, NT_SMEM>>>(
            M, Dd, DFF, F, DFF, W2r + (size_t)l * Dd * DFF, DFF, Hb, Dd, B2p + l * Dd);

        float* outp = (l == LL - 1) ? (float*)d_out : X;
        float* outr = (l == LL - 1) ? nullptr : Xr;
        add_ln_kernel<<<M / 8, 256>>>(Y1, Hb, L2g + l * Dd, L2b + l * Dd, outp, outr, (l == LL - 1) ? 1 : 0);
    }
}